// round 7
// baseline (speedup 1.0000x reference)
#include <cuda_runtime.h>
#include <math.h>

#define MAX_RAYS 65536
__device__ int g_seg[MAX_RAYS + 1];
__device__ int g_mMin;   // int-encoded min of (ts+te)  (positive floats)
__device__ int g_mMax;   // int-encoded max of (ts+te)

typedef unsigned long long ull;

// ---- packed f32x2 helpers (Blackwell) -------------------------------------
__device__ __forceinline__ ull f2fma(ull a, ull b, ull c) {
    ull d;
    asm("fma.rn.f32x2 %0, %1, %2, %3;" : "=l"(d) : "l"(a), "l"(b), "l"(c));
    return d;
}
__device__ __forceinline__ ull f2add(ull a, ull b) {
    ull d;
    asm("add.rn.f32x2 %0, %1, %2;" : "=l"(d) : "l"(a), "l"(b));
    return d;
}
__device__ __forceinline__ ull f2pack(float lo, float hi) {
    ull d;
    asm("mov.b64 %0, {%1, %2};" : "=l"(d) : "f"(lo), "f"(hi));
    return d;
}
__device__ __forceinline__ void f2unpack(ull v, float& lo, float& hi) {
    asm("mov.b64 {%0, %1}, %2;" : "=f"(lo), "=f"(hi) : "l"(v));
}
#define ABSMASK 0x7FFFFFFF7FFFFFFFULL

__global__ void init_kernel() {
    g_mMin = 0x7F800000;   // +inf
    g_mMax = 0;            // +0.0
}

// ---------------------------------------------------------------------------
// Kernel A: segment starts from sorted ray_indices + global min/max of ts+te.
// ---------------------------------------------------------------------------
__global__ void seg_boundary_kernel(const int* __restrict__ ri,
                                    const float* __restrict__ ts,
                                    const float* __restrict__ te,
                                    int S, int n_rays) {
    const int i    = blockIdx.x * blockDim.x + threadIdx.x;
    const int lane = threadIdx.x & 31;

    // --- min/max of m = ts+te (all positive -> int compare valid) ----------
    float mn = __int_as_float(0x7F800000);
    float mx = 0.f;
    if (i < S) { const float m = ts[i] + te[i]; mn = m; mx = m; }
    #pragma unroll
    for (int off = 16; off; off >>= 1) {
        mn = fminf(mn, __shfl_xor_sync(0xffffffffu, mn, off));
        mx = fmaxf(mx, __shfl_xor_sync(0xffffffffu, mx, off));
    }
    if (lane == 0) {
        atomicMin(&g_mMin, __float_as_int(mn));
        atomicMax(&g_mMax, __float_as_int(mx));
    }

    if (i >= S) return;
    const int r  = ri[i];
    const int rp = (i == 0) ? -1 : ri[i - 1];
    for (int rr = rp + 1; rr <= r; ++rr) g_seg[rr] = i;
    if (i == S - 1) {
        for (int rr = r + 1; rr <= n_rays; ++rr) g_seg[rr] = S;
    }
}

// ---------------------------------------------------------------------------
// Kernel B: one warp per ray. MLP collapsed to 1-D:
//   acc(t) = A t + C + Sum_j sign(w2_j) |u_j t + v_j| ,
//   u = 0.5 w2 (d.W1_j), v = 0.5 w2 (o.W1_j + b1_j).
// Units whose |u t + v| keeps constant sign over [ta,tb] (the global sample
// t-midpoint range) are EXACTLY linear -> folded into (A,C) at precompute.
// Remaining "active" units are ballot-compacted into per-warp shared lists
// (positive-w2 group, then negative-w2 group, each zero-padded to even) and
// summed packed-f32x2 in the sample loop.
// ---------------------------------------------------------------------------
__global__ void __launch_bounds__(256, 4) render_kernel(
    const float* __restrict__ rays_o,
    const float* __restrict__ rays_d,
    const float* __restrict__ W1,
    const float* __restrict__ b1,
    const float* __restrict__ W2,
    const float* __restrict__ b2,
    const float* __restrict__ t_starts,
    const float* __restrict__ t_ends,
    float* __restrict__ out,
    int n_rays)
{
    __shared__ ull uAll[8][36];   // per-warp active u list (float pairs)
    __shared__ ull vAll[8][36];   // per-warp active v list

    const int wlocal  = threadIdx.x >> 5;
    const int lane    = threadIdx.x & 31;
    const int warp_id = (blockIdx.x * blockDim.x + threadIdx.x) >> 5;
    if (warp_id >= n_rays) return;
    const int r = warp_id;

    const int start = g_seg[r];
    const int end   = g_seg[r + 1];

    const float ox = __ldg(&rays_o[3 * r    ]);
    const float oy = __ldg(&rays_o[3 * r + 1]);
    const float oz = __ldg(&rays_o[3 * r + 2]);
    const float dx = __ldg(&rays_d[3 * r    ]);
    const float dy = __ldg(&rays_d[3 * r + 1]);
    const float dz = __ldg(&rays_d[3 * r + 2]);

    const float ta = 0.5f * __int_as_float(g_mMin);
    const float tb = 0.5f * __int_as_float(g_mMax);

    // ---- per-ray precompute: lane handles units 2*lane, 2*lane+1 ----------
    float A = 0.f, C = 0.f;
    float u0, v0, u1, v1;
    bool act0, act1, pos0, pos1;
    {
        const int j = 2 * lane;
        #pragma unroll
        for (int k = 0; k < 2; ++k) {
            const int jj = j + k;
            const float w1x = __ldg(&W1[jj]);
            const float w1y = __ldg(&W1[64 + jj]);
            const float w1z = __ldg(&W1[128 + jj]);
            const float bb  = __ldg(&b1[jj]);
            const float w2v = __ldg(&W2[jj]);
            const float hw  = 0.5f * w2v;

            const float a = fmaf(dx, w1x, fmaf(dy, w1y, dz * w1z));
            const float c = fmaf(ox, w1x, fmaf(oy, w1y, fmaf(oz, w1z, bb)));
            const float u = hw * a;
            const float v = hw * c;

            A += u;           // linear part Sum y
            C += v;

            const float ya = fmaf(u, ta, v);
            const float yb = fmaf(u, tb, v);
            const bool act = (((__float_as_uint(ya) ^ __float_as_uint(yb)) >> 31) & 1u) != 0u;
            if (!act) {
                // foldable: extra term f*y, f = sign(w2)*sign(y)
                const float f = copysignf(1.f, ya + yb) * copysignf(1.f, w2v);
                A = fmaf(f, u, A);
                C = fmaf(f, v, C);
            }
            if (k == 0) { u0 = u; v0 = v; act0 = act; pos0 = (w2v >= 0.f); }
            else        { u1 = u; v1 = v; act1 = act; pos1 = (w2v >= 0.f); }
        }

        #pragma unroll
        for (int off = 16; off; off >>= 1) {
            A += __shfl_xor_sync(0xffffffffu, A, off);
            C += __shfl_xor_sync(0xffffffffu, C, off);
        }
        C += __ldg(b2);
    }

    // ---- ballot compaction of active units into shared lists --------------
    float* uF = (float*)uAll[wlocal];
    float* vF = (float*)vAll[wlocal];

    const unsigned bp0 = __ballot_sync(0xffffffffu, act0 && pos0);
    const unsigned bn0 = __ballot_sync(0xffffffffu, act0 && !pos0);
    const unsigned bp1 = __ballot_sync(0xffffffffu, act1 && pos1);
    const unsigned bn1 = __ballot_sync(0xffffffffu, act1 && !pos1);
    const int cP0 = __popc(bp0), cN0 = __popc(bn0);
    const int cP1 = __popc(bp1), cN1 = __popc(bn1);
    const int nPos = cP0 + cP1;
    const int nNeg = cN0 + cN1;
    const int negBase = (nPos + 1) & ~1;

    const unsigned mlt = (1u << lane) - 1u;
    if (act0) {
        const int ix = pos0 ? __popc(bp0 & mlt) : (negBase + __popc(bn0 & mlt));
        uF[ix] = u0; vF[ix] = v0;
    }
    if (act1) {
        const int ix = pos1 ? (cP0 + __popc(bp1 & mlt))
                            : (negBase + cN0 + __popc(bn1 & mlt));
        uF[ix] = u1; vF[ix] = v1;
    }
    if (lane == 0) {
        if (nPos & 1) { uF[nPos] = 0.f; vF[nPos] = 0.f; }
        if (nNeg & 1) { uF[negBase + nNeg] = 0.f; vF[negBase + nNeg] = 0.f; }
    }
    __syncwarp();

    const int pPos      = (nPos + 1) >> 1;            // packed pos pairs
    const int pNegStart = negBase >> 1;
    const int pNegEnd   = pNegStart + ((nNeg + 1) >> 1);
    const ull* uu = uAll[wlocal];
    const ull* vv = vAll[wlocal];

    float carry = 0.f;
    float opac  = 0.f;
    float dnum  = 0.f;

    for (int i0 = start; i0 < end; i0 += 32) {
        const int  i     = i0 + lane;
        const bool valid = (i < end);
        const int  ic    = valid ? i : (end - 1);

        const float tsv = t_starts[ic];
        const float tev = t_ends[ic];
        const float tm  = 0.5f * (tsv + tev);
        const float dt  = tev - tsv;
        const ull   t2  = f2pack(tm, tm);

        ull accP = 0ull, accN = 0ull;
        #pragma unroll 2
        for (int p = 0; p < pPos; ++p) {
            const ull y = f2fma(t2, uu[p], vv[p]);
            accP = f2add(accP, y & ABSMASK);
        }
        #pragma unroll 2
        for (int p = pNegStart; p < pNegEnd; ++p) {
            const ull y = f2fma(t2, uu[p], vv[p]);
            accN = f2add(accN, y & ABSMASK);
        }

        float pl, ph, nl, nh;
        f2unpack(accP, pl, ph);
        f2unpack(accN, nl, nh);
        const float acc = fmaf(A, tm, C) + (pl + ph) - (nl + nh);

        // softplus(x) = max(x,0) + log(1 + exp(-|x|))
        const float sp = fmaxf(acc, 0.f) + __logf(1.f + __expf(-fabsf(acc)));
        const float s  = valid ? sp * dt : 0.f;

        // warp-inclusive scan of s
        float incl = s;
        #pragma unroll
        for (int off = 1; off < 32; off <<= 1) {
            float v = __shfl_up_sync(0xffffffffu, incl, off);
            if (lane >= off) incl += v;
        }
        const float excl = incl - s;

        // w = e^{-(carry+excl)} - e^{-(carry+incl)} ; exactly 0 when s==0
        const float w = __expf(-(carry + excl)) - __expf(-(carry + incl));
        opac += w;
        dnum  = fmaf(w, tm, dnum);
        carry += __shfl_sync(0xffffffffu, incl, 31);
    }

    #pragma unroll
    for (int off = 16; off; off >>= 1) {
        opac += __shfl_xor_sync(0xffffffffu, opac, off);
        dnum += __shfl_xor_sync(0xffffffffu, dnum, off);
    }

    if (lane == 0) {
        const float depth = dnum / fmaxf(opac, 1.17549435e-38f);
        out[2 * r    ] = opac;
        out[2 * r + 1] = depth;
    }
}

extern "C" void kernel_launch(void* const* d_in, const int* in_sizes, int n_in,
                              void* d_out, int out_size) {
    const float* rays_o      = (const float*)d_in[0];
    const float* rays_d      = (const float*)d_in[1];
    const float* W1          = (const float*)d_in[2];
    const float* b1          = (const float*)d_in[3];
    const float* W2          = (const float*)d_in[4];
    const float* b2          = (const float*)d_in[5];
    const float* t_starts    = (const float*)d_in[6];
    const float* t_ends      = (const float*)d_in[7];
    const int*   ray_indices = (const int*)d_in[8];

    const int S      = in_sizes[6];
    const int n_rays = in_sizes[0] / 3;

    float* out = (float*)d_out;

    init_kernel<<<1, 1>>>();
    seg_boundary_kernel<<<(S + 255) / 256, 256>>>(ray_indices, t_starts, t_ends, S, n_rays);

    const int warps_per_block = 8;
    const int blocks = (n_rays + warps_per_block - 1) / warps_per_block;
    render_kernel<<<blocks, warps_per_block * 32>>>(
        rays_o, rays_d, W1, b1, W2, b2, t_starts, t_ends, out, n_rays);
}

// round 8
// speedup vs baseline: 2.1027x; 2.1027x over previous
#include <cuda_runtime.h>
#include <math.h>

#define MAX_RAYS 65536
__device__ int g_seg[MAX_RAYS + 1];

typedef unsigned long long ull;

// ---- packed f32x2 helpers (Blackwell) -------------------------------------
__device__ __forceinline__ ull f2fma(ull a, ull b, ull c) {
    ull d;
    asm("fma.rn.f32x2 %0, %1, %2, %3;" : "=l"(d) : "l"(a), "l"(b), "l"(c));
    return d;
}
__device__ __forceinline__ ull f2add(ull a, ull b) {
    ull d;
    asm("add.rn.f32x2 %0, %1, %2;" : "=l"(d) : "l"(a), "l"(b));
    return d;
}
__device__ __forceinline__ ull f2pack(float lo, float hi) {
    ull d;
    asm("mov.b64 %0, {%1, %2};" : "=l"(d) : "f"(lo), "f"(hi));
    return d;
}
__device__ __forceinline__ void f2unpack(ull v, float& lo, float& hi) {
    asm("mov.b64 {%0, %1}, %2;" : "=f"(lo), "=f"(hi) : "l"(v));
}
#define ABSMASK 0x7FFFFFFF7FFFFFFFULL

// ---------------------------------------------------------------------------
// Kernel A: segment starts from sorted ray_indices (searchsorted).
// ---------------------------------------------------------------------------
__global__ void seg_boundary_kernel(const int* __restrict__ ri, int S, int n_rays) {
    const int i = blockIdx.x * blockDim.x + threadIdx.x;
    if (i >= S) return;
    const int r  = ri[i];
    const int rp = (i == 0) ? -1 : ri[i - 1];
    for (int rr = rp + 1; rr <= r; ++rr) g_seg[rr] = i;
    if (i == S - 1) {
        for (int rr = r + 1; rr <= n_rays; ++rr) g_seg[rr] = S;
    }
}

// ---------------------------------------------------------------------------
// Kernel B: one warp per ray. MLP collapsed to 1-D in t:
//   acc(t) = A t + C + Sum_j sign(w2_j)|u_j t + v_j|,
//   u = 0.5 w2 (d.W1_j), v = 0.5 w2 (o.W1_j + b1_j).
// Per-ray t-bounds [ta,tb] come from a warp pre-pass over this ray's own tm
// values (identical expression as the main loop -> bounds are exact).
// Units with constant ReLU sign over [ta,tb] fold exactly into (A,C).
// Active units ballot-compacted into per-warp shared lists (pos group, neg
// group, each even-padded) -> short packed-f32x2 abs-sum loop.
// ---------------------------------------------------------------------------
__global__ void __launch_bounds__(256, 4) render_kernel(
    const float* __restrict__ rays_o,
    const float* __restrict__ rays_d,
    const float* __restrict__ W1,
    const float* __restrict__ b1,
    const float* __restrict__ W2,
    const float* __restrict__ b2,
    const float* __restrict__ t_starts,
    const float* __restrict__ t_ends,
    float* __restrict__ out,
    int n_rays)
{
    __shared__ ull uAll[8][36];
    __shared__ ull vAll[8][36];

    const int wlocal  = threadIdx.x >> 5;
    const int lane    = threadIdx.x & 31;
    const int warp_id = (blockIdx.x * blockDim.x + threadIdx.x) >> 5;
    if (warp_id >= n_rays) return;
    const int r = warp_id;

    const int start = g_seg[r];
    const int end   = g_seg[r + 1];

    const float ox = __ldg(&rays_o[3 * r    ]);
    const float oy = __ldg(&rays_o[3 * r + 1]);
    const float oz = __ldg(&rays_o[3 * r + 2]);
    const float dx = __ldg(&rays_d[3 * r    ]);
    const float dy = __ldg(&rays_d[3 * r + 1]);
    const float dz = __ldg(&rays_d[3 * r + 2]);

    // ---- pre-pass: exact per-ray min/max of tm -----------------------------
    float ta = __int_as_float(0x7F800000);   // +inf
    float tb = 0.f;
    for (int i0 = start; i0 < end; i0 += 32) {
        const int i = i0 + lane;
        if (i < end) {
            const float tm = 0.5f * (t_starts[i] + t_ends[i]);
            ta = fminf(ta, tm);
            tb = fmaxf(tb, tm);
        }
    }
    #pragma unroll
    for (int off = 16; off; off >>= 1) {
        ta = fminf(ta, __shfl_xor_sync(0xffffffffu, ta, off));
        tb = fmaxf(tb, __shfl_xor_sync(0xffffffffu, tb, off));
    }

    // ---- per-ray precompute: lane handles units 2*lane, 2*lane+1 ----------
    float A = 0.f, C = 0.f;
    float u0, v0, u1, v1;
    bool act0, act1, pos0, pos1;
    {
        const int j = 2 * lane;
        #pragma unroll
        for (int k = 0; k < 2; ++k) {
            const int jj = j + k;
            const float w1x = __ldg(&W1[jj]);
            const float w1y = __ldg(&W1[64 + jj]);
            const float w1z = __ldg(&W1[128 + jj]);
            const float bb  = __ldg(&b1[jj]);
            const float w2v = __ldg(&W2[jj]);
            const float hw  = 0.5f * w2v;

            const float a = fmaf(dx, w1x, fmaf(dy, w1y, dz * w1z));
            const float c = fmaf(ox, w1x, fmaf(oy, w1y, fmaf(oz, w1z, bb)));
            const float u = hw * a;
            const float v = hw * c;

            A += u;
            C += v;

            const float ya = fmaf(u, ta, v);
            const float yb = fmaf(u, tb, v);
            const bool act = (((__float_as_uint(ya) ^ __float_as_uint(yb)) >> 31) & 1u) != 0u;
            if (!act) {
                const float f = copysignf(1.f, ya + yb) * copysignf(1.f, w2v);
                A = fmaf(f, u, A);
                C = fmaf(f, v, C);
            }
            if (k == 0) { u0 = u; v0 = v; act0 = act; pos0 = (w2v >= 0.f); }
            else        { u1 = u; v1 = v; act1 = act; pos1 = (w2v >= 0.f); }
        }

        #pragma unroll
        for (int off = 16; off; off >>= 1) {
            A += __shfl_xor_sync(0xffffffffu, A, off);
            C += __shfl_xor_sync(0xffffffffu, C, off);
        }
        C += __ldg(b2);
    }

    // ---- ballot compaction of active units into shared lists --------------
    float* uF = (float*)uAll[wlocal];
    float* vF = (float*)vAll[wlocal];

    const unsigned bp0 = __ballot_sync(0xffffffffu, act0 && pos0);
    const unsigned bn0 = __ballot_sync(0xffffffffu, act0 && !pos0);
    const unsigned bp1 = __ballot_sync(0xffffffffu, act1 && pos1);
    const unsigned bn1 = __ballot_sync(0xffffffffu, act1 && !pos1);
    const int cP0 = __popc(bp0), cN0 = __popc(bn0);
    const int cP1 = __popc(bp1), cN1 = __popc(bn1);
    const int nPos = cP0 + cP1;
    const int nNeg = cN0 + cN1;
    const int negBase = (nPos + 1) & ~1;

    const unsigned mlt = (1u << lane) - 1u;
    if (act0) {
        const int ix = pos0 ? __popc(bp0 & mlt) : (negBase + __popc(bn0 & mlt));
        uF[ix] = u0; vF[ix] = v0;
    }
    if (act1) {
        const int ix = pos1 ? (cP0 + __popc(bp1 & mlt))
                            : (negBase + cN0 + __popc(bn1 & mlt));
        uF[ix] = u1; vF[ix] = v1;
    }
    if (lane == 0) {
        if (nPos & 1) { uF[nPos] = 0.f; vF[nPos] = 0.f; }
        if (nNeg & 1) { uF[negBase + nNeg] = 0.f; vF[negBase + nNeg] = 0.f; }
    }
    __syncwarp();

    const int pPos      = (nPos + 1) >> 1;
    const int pNegStart = negBase >> 1;
    const int pNegEnd   = pNegStart + ((nNeg + 1) >> 1);
    const ull* uu = uAll[wlocal];
    const ull* vv = vAll[wlocal];

    float carry = 0.f;
    float opac  = 0.f;
    float dnum  = 0.f;

    for (int i0 = start; i0 < end; i0 += 32) {
        const int  i     = i0 + lane;
        const bool valid = (i < end);
        const int  ic    = valid ? i : (end - 1);

        const float tsv = t_starts[ic];
        const float tev = t_ends[ic];
        const float tm  = 0.5f * (tsv + tev);
        const float dt  = tev - tsv;
        const ull   t2  = f2pack(tm, tm);

        ull accP = 0ull, accN = 0ull;
        #pragma unroll 4
        for (int p = 0; p < pPos; ++p) {
            const ull y = f2fma(t2, uu[p], vv[p]);
            accP = f2add(accP, y & ABSMASK);
        }
        #pragma unroll 4
        for (int p = pNegStart; p < pNegEnd; ++p) {
            const ull y = f2fma(t2, uu[p], vv[p]);
            accN = f2add(accN, y & ABSMASK);
        }

        float pl, ph, nl, nh;
        f2unpack(accP, pl, ph);
        f2unpack(accN, nl, nh);
        const float acc = fmaf(A, tm, C) + (pl + ph) - (nl + nh);

        // softplus(x) = max(x,0) + log(1 + exp(-|x|))
        const float sp = fmaxf(acc, 0.f) + __logf(1.f + __expf(-fabsf(acc)));
        const float s  = valid ? sp * dt : 0.f;

        // warp-inclusive scan of s
        float incl = s;
        #pragma unroll
        for (int off = 1; off < 32; off <<= 1) {
            float v = __shfl_up_sync(0xffffffffu, incl, off);
            if (lane >= off) incl += v;
        }
        const float excl = incl - s;

        // w = e^{-(carry+excl)} - e^{-(carry+incl)} ; exactly 0 when s==0
        const float w = __expf(-(carry + excl)) - __expf(-(carry + incl));
        opac += w;
        dnum  = fmaf(w, tm, dnum);
        carry += __shfl_sync(0xffffffffu, incl, 31);
    }

    #pragma unroll
    for (int off = 16; off; off >>= 1) {
        opac += __shfl_xor_sync(0xffffffffu, opac, off);
        dnum += __shfl_xor_sync(0xffffffffu, dnum, off);
    }

    if (lane == 0) {
        const float depth = dnum / fmaxf(opac, 1.17549435e-38f);
        out[2 * r    ] = opac;
        out[2 * r + 1] = depth;
    }
}

extern "C" void kernel_launch(void* const* d_in, const int* in_sizes, int n_in,
                              void* d_out, int out_size) {
    const float* rays_o      = (const float*)d_in[0];
    const float* rays_d      = (const float*)d_in[1];
    const float* W1          = (const float*)d_in[2];
    const float* b1          = (const float*)d_in[3];
    const float* W2          = (const float*)d_in[4];
    const float* b2          = (const float*)d_in[5];
    const float* t_starts    = (const float*)d_in[6];
    const float* t_ends      = (const float*)d_in[7];
    const int*   ray_indices = (const int*)d_in[8];

    const int S      = in_sizes[6];
    const int n_rays = in_sizes[0] / 3;

    float* out = (float*)d_out;

    seg_boundary_kernel<<<(S + 255) / 256, 256>>>(ray_indices, S, n_rays);

    const int warps_per_block = 8;
    const int blocks = (n_rays + warps_per_block - 1) / warps_per_block;
    render_kernel<<<blocks, warps_per_block * 32>>>(
        rays_o, rays_d, W1, b1, W2, b2, t_starts, t_ends, out, n_rays);
}